// round 15
// baseline (speedup 1.0000x reference)
#include <cuda_runtime.h>
#include <cstdint>

// out[b,t,:] = tok_weight[x[b,t],:] + pos_weight[t,:]
// B=4, T=4096, E=512 fp32.
//
// FINAL (converged at hardware roofline, 10.69us):
// Mandatory memory traffic per launch:
//   - 33.5MB output writes  (drains to DRAM at ~3TB/s write-stream rate)
//   - 33.5MB tok gathers    (~7.6MB unavoidable duplicates; L2-resident reads)
//   - 8.4MB  pos reads      (register-deduped 4x across the batch dim)
//   => ~75.5MB LTS traffic @ measured path-independent cap (~6300 B/cyc)
//   => ~10.7us floor; both the DRAM-write drain and the LTS cap models
//      predict the observed plateau.
// 14 structural variants (occupancy 35-74%, MLP 2-13, 128/256-bit, wb/cs/
// evict_last/evict_first policies, TMA bulk load+store pipelines, packed
// f32x2 math, serialized vs batched chains) are all within +-3% of this
// number. The only remaining lever (persisting-L2 carveout to keep the
// output resident across graph replays) is forbidden by the harness.
//
// Structure (empirical best): one warp per (t, column-half); the 4 batch
// rows share pos_weight[t] held in registers; 8 independent 128-bit gathers
// in flight; streaming stores.

__global__ void __launch_bounds__(256) pos_embed_kernel(
    const int* __restrict__ x,            // [4*T]
    const float4* __restrict__ tok_w,     // [VOCAB, 128] float4
    const float4* __restrict__ pos_w,     // [T, 128] float4
    float4* __restrict__ out,             // [4*T, 128] float4
    int T)                                // 4096
{
    const int wid_global = blockIdx.x * (blockDim.x >> 5) + (threadIdx.x >> 5);
    const int t    = wid_global >> 1;          // time step
    const int half = wid_global & 1;           // which 64-float4 half of row
    if (t >= T) return;
    const int lane = threadIdx.x & 31;
    const int col  = half * 64 + lane;         // float4 column (+0, +32)

    // Hoisted index loads: one L2 latency for all four.
    const int tok0 = __ldg(&x[t]);
    const int tok1 = __ldg(&x[t + T]);
    const int tok2 = __ldg(&x[t + 2 * T]);
    const int tok3 = __ldg(&x[t + 3 * T]);

    const float4* __restrict__ pp = pos_w + (long long)t * 128 + col;
    const float4* __restrict__ t0 = tok_w + (long long)tok0 * 128 + col;
    const float4* __restrict__ t1 = tok_w + (long long)tok1 * 128 + col;
    const float4* __restrict__ t2 = tok_w + (long long)tok2 * 128 + col;
    const float4* __restrict__ t3 = tok_w + (long long)tok3 * 128 + col;
    float4* __restrict__ o0 = out + (long long)t * 128 + col;             // b=0
    float4* __restrict__ o1 = o0 + (long long)T * 128;                    // b=1
    float4* __restrict__ o2 = o1 + (long long)T * 128;                    // b=2
    float4* __restrict__ o3 = o2 + (long long)T * 128;                    // b=3

    // pos half-row in registers, reused by all 4 batches
    float4 p0 = __ldg(pp +  0);
    float4 p1 = __ldg(pp + 32);

    // 8 independent gathers in flight
    float4 a0 = __ldg(t0 +  0), a1 = __ldg(t0 + 32);
    float4 b0 = __ldg(t1 +  0), b1 = __ldg(t1 + 32);
    float4 c0 = __ldg(t2 +  0), c1 = __ldg(t2 + 32);
    float4 d0 = __ldg(t3 +  0), d1 = __ldg(t3 + 32);

    float4 r;
    r.x = a0.x + p0.x; r.y = a0.y + p0.y; r.z = a0.z + p0.z; r.w = a0.w + p0.w; __stcs(o0 +  0, r);
    r.x = a1.x + p1.x; r.y = a1.y + p1.y; r.z = a1.z + p1.z; r.w = a1.w + p1.w; __stcs(o0 + 32, r);
    r.x = b0.x + p0.x; r.y = b0.y + p0.y; r.z = b0.z + p0.z; r.w = b0.w + p0.w; __stcs(o1 +  0, r);
    r.x = b1.x + p1.x; r.y = b1.y + p1.y; r.z = b1.z + p1.z; r.w = b1.w + p1.w; __stcs(o1 + 32, r);
    r.x = c0.x + p0.x; r.y = c0.y + p0.y; r.z = c0.z + p0.z; r.w = c0.w + p0.w; __stcs(o2 +  0, r);
    r.x = c1.x + p1.x; r.y = c1.y + p1.y; r.z = c1.z + p1.z; r.w = c1.w + p1.w; __stcs(o2 + 32, r);
    r.x = d0.x + p0.x; r.y = d0.y + p0.y; r.z = d0.z + p0.z; r.w = d0.w + p0.w; __stcs(o3 +  0, r);
    r.x = d1.x + p1.x; r.y = d1.y + p1.y; r.z = d1.z + p1.z; r.w = d1.w + p1.w; __stcs(o3 + 32, r);
}

extern "C" void kernel_launch(void* const* d_in, const int* in_sizes, int n_in,
                              void* d_out, int out_size) {
    const int*    x     = (const int*)d_in[0];
    const float4* tok_w = (const float4*)d_in[1];
    const float4* pos_w = (const float4*)d_in[2];
    float4*       out   = (float4*)d_out;

    const int T = 4096;                       // fixed problem shape (B=4)
    const int total_warps = T * 2;            // (t, half) = 8192
    const int threads = 256;                  // 8 warps/block
    const int warps_per_blk = threads / 32;
    int blocks = (total_warps + warps_per_blk - 1) / warps_per_blk;  // 1024

    pos_embed_kernel<<<blocks, threads>>>(x, tok_w, pos_w, out, T);
}